// round 6
// baseline (speedup 1.0000x reference)
#include <cuda_runtime.h>

#define GA 148           // MLP/gate blocks
#define GB 148           // H-stream blocks
#define NBLK (GA + GB)
#define BSTRIDE (GB * 8) // elems per B sweep (one per B-warp)
#define MAXB 65536

__device__ float g_outB[MAXB * 8];  // H-stream partial outputs

__device__ __forceinline__ float sigm(float v) { return 1.0f / (1.0f + __expf(-v)); }

__device__ __forceinline__ unsigned long long ffma2(unsigned long long a,
                                                    unsigned long long b,
                                                    unsigned long long c) {
    unsigned long long d;
    asm("fma.rn.f32x2 %0, %1, %2, %3;" : "=l"(d) : "l"(a), "l"(b), "l"(c));
    return d;
}
union f4u { float4 f; unsigned long long u[2]; };

__device__ __forceinline__ void cp16(unsigned s, const void* g) {
    asm volatile("cp.async.cg.shared.global [%0], [%1], 16;" :: "r"(s), "l"(g));
}
#define CP_COMMIT() asm volatile("cp.async.commit_group;" ::: "memory")
#define CP_WAIT3()  asm volatile("cp.async.wait_group 3;" ::: "memory")
#define CP_WAIT0()  asm volatile("cp.async.wait_group 0;" ::: "memory")

// ---------------- shared layouts ------------------------------------------------------------
struct SmemA {                      // ~64.7 KB
    float Wr[8][512];
    float WbT[32][64];
    float WshT[64][64];
    float haltT[64][32];
    float s2s[8][4][64];
    float s1s[8][4][32];
    float gss[8][4][8];
    float WbitT[8][32];
    float Weng[64], Wimp[64];
    float Wsur[32], Wgate[32];
    float bbit[32], bsh[64];
    float bread[8];
    float haltb[4];
    float beng, bimp, bsur, bgate;
};
struct SmemB {                      // 88 KB
    float dg[2048];
    float Wr[8][512];
    float buf[8][4][512];           // [warp][slice l][j]  (512 floats = 2048 B per slice)
};
union SmemU { SmemA a; SmemB b; };

__global__ void __launch_bounds__(256, 2)
org_mixed(const float* __restrict__ x, const float* __restrict__ H,
          const float* __restrict__ W_bit, const float* __restrict__ b_bit,
          const float* __restrict__ W_bridge, const float* __restrict__ W_read,
          const float* __restrict__ b_read, const float* __restrict__ W_sh,
          const float* __restrict__ b_sh, const float* __restrict__ W_eng,
          const float* __restrict__ b_eng, const float* __restrict__ W_imp,
          const float* __restrict__ b_imp, const float* __restrict__ W_sur,
          const float* __restrict__ b_sur, const float* __restrict__ W_gate,
          const float* __restrict__ b_gate, const float* __restrict__ decays,
          const float* __restrict__ halt_w, const float* __restrict__ halt_b,
          float* __restrict__ out, int B)
{
    extern __shared__ float smraw[];
    SmemU* Su = reinterpret_cast<SmemU*>(smraw);
    const int tid = threadIdx.x;
    const int warp = tid >> 5, lane = tid & 31;
    const unsigned FULL = 0xffffffffu;

    if (blockIdx.x >= GA) {
        // ===================== B path: cp.async-pipelined H stream ========================
        SmemB* Sb = &Su->b;
        for (int i = tid; i < 2048; i += 256) Sb->dg[i] = sigm(decays[i]);
        for (int i = tid; i < 4096; i += 256) (&Sb->Wr[0][0])[i] = 0.25f * W_read[i];
        __syncthreads();

        float* bufw = &Sb->buf[warp][0][0];
        unsigned bufu = (unsigned)__cvta_generic_to_shared(bufw) + lane * 16u;

        int e = ((int)blockIdx.x - GA) * 8 + warp;

        // prologue: stage all 4 slices of first elem (4 commit groups)
        {
            const float* Hg = H + (size_t)e * 2048 + lane * 4;
            #pragma unroll
            for (int l = 0; l < 4; ++l) {
                #pragma unroll
                for (int c = 0; c < 4; ++c)
                    cp16(bufu + (unsigned)(l * 2048 + c * 512), Hg + l * 512 + c * 128);
                CP_COMMIT();
            }
        }

        while (e < B) {
            int en = e + BSTRIDE;
            int ec = (en < B) ? en : 0;             // clamped refill source (discarded)
            const float* Hn = H + (size_t)ec * 2048 + lane * 4;

            f4u rs[4];
            #pragma unroll
            for (int c = 0; c < 4; ++c) rs[c].f = make_float4(0.f, 0.f, 0.f, 0.f);

            #pragma unroll
            for (int l = 0; l < 4; ++l) {
                CP_WAIT3();                          // oldest group (slice l) has landed
                #pragma unroll
                for (int c = 0; c < 4; ++c) {
                    // FLOAT index (bug fix): matches byte offset l*2048B + c*512B + lane*16B
                    f4u t; t.f = *(const float4*)&bufw[l * 512 + c * 128 + lane * 4];
                    f4u d; d.f = *(const float4*)&Sb->dg[l * 512 + c * 128 + lane * 4];
                    rs[c].u[0] = ffma2(t.u[0], d.u[0], rs[c].u[0]);
                    rs[c].u[1] = ffma2(t.u[1], d.u[1], rs[c].u[1]);
                }
                // refill slice l with next element's slice l
                #pragma unroll
                for (int c = 0; c < 4; ++c)
                    cp16(bufu + (unsigned)(l * 2048 + c * 512), Hn + l * 512 + c * 128);
                CP_COMMIT();
            }

            // readout: p[o] = sum_j rs_j * Wr4[o][j]
            #pragma unroll
            for (int o = 0; o < 8; ++o) {
                unsigned long long a0 = 0ull, a1 = 0ull;
                #pragma unroll
                for (int c = 0; c < 4; ++c) {
                    f4u w; w.f = *(const float4*)&Sb->Wr[o][c * 128 + lane * 4];
                    a0 = ffma2(rs[c].u[0], w.u[0], a0);
                    a1 = ffma2(rs[c].u[1], w.u[1], a1);
                }
                f4u pa; pa.u[0] = a0; pa.u[1] = a1;
                float p = (pa.f.x + pa.f.y) + (pa.f.z + pa.f.w);
                #pragma unroll
                for (int s = 16; s; s >>= 1) p += __shfl_xor_sync(FULL, p, s);
                if (lane == o) g_outB[(size_t)e * 8 + o] = p;
            }
            e = en;
        }
        CP_WAIT0();
        return;
    }

    // ===================== A path: MLP + gate-term readout =============================
    SmemA* S = &Su->a;
    for (int i = tid; i < 4096; i += 256) (&S->Wr[0][0])[i] = 0.25f * W_read[i];
    for (int i = tid; i < 2048; i += 256) { int k = i >> 6, m = i & 63; (&S->WbT[0][0])[i]   = W_bridge[m * 32 + k]; }
    for (int i = tid; i < 4096; i += 256) { int m = i >> 6, o = i & 63; (&S->WshT[0][0])[i]  = W_sh[o * 64 + m]; }
    for (int i = tid; i < 2048; i += 256) { int m = i >> 5, s = i & 31; (&S->haltT[0][0])[i] = halt_w[s * 64 + m]; }
    (&S->WbitT[0][0])[tid] = W_bit[(tid & 31) * 8 + (tid >> 5)];
    if (tid < 64) { S->Weng[tid] = W_eng[tid]; S->Wimp[tid] = W_imp[tid]; S->bsh[tid] = b_sh[tid]; }
    if (tid < 32) { S->Wsur[tid] = W_sur[tid]; S->Wgate[tid] = W_gate[tid]; S->bbit[tid] = b_bit[tid]; }
    if (tid < 8)  S->bread[tid] = b_read[tid];
    if (tid < 4)  S->haltb[tid] = halt_b[tid];
    if (tid == 0) { S->beng = b_eng[0]; S->bimp = b_imp[0]; S->bsur = b_sur[0]; S->bgate = b_gate[0]; }
    __syncthreads();

    float* s1w  = &S->s1s[warp][0][0];
    float* s2w  = &S->s2s[warp][0][0];
    float* gssw = &S->gss[warp][0][0];

    for (int e0 = blockIdx.x * 32 + warp * 4; e0 < B; e0 += GA * 32) {
        // ---- s1 ----
        float xv = x[(size_t)e0 * 8 + lane];
        float s1v[4];
        #pragma unroll
        for (int e = 0; e < 4; ++e) {
            float a = S->bbit[lane];
            #pragma unroll
            for (int j = 0; j < 8; ++j) {
                float xj = __shfl_sync(FULL, xv, e * 8 + j);
                a = fmaf(xj, S->WbitT[j][lane], a);
            }
            s1v[e] = a;
            s1w[e * 32 + lane] = a;
        }
        // ---- surprise ----
        float sur[4];
        #pragma unroll
        for (int e = 0; e < 4; ++e) {
            float a = s1v[e] * S->Wsur[lane];
            float b = s1v[e] * S->Wgate[lane];
            #pragma unroll
            for (int s = 16; s; s >>= 1) {
                a += __shfl_xor_sync(FULL, a, s);
                b += __shfl_xor_sync(FULL, b, s);
            }
            sur[e] = sigm(a + S->bsur) * sigm(b + S->bgate);
        }
        __syncwarp();

        // ---- s2 = tanh(s1 @ Wb^T) ----
        {
            float acc0[4] = {0,0,0,0}, acc1[4] = {0,0,0,0};
            #pragma unroll
            for (int k4 = 0; k4 < 8; ++k4) {
                float4 s14[4];
                #pragma unroll
                for (int e = 0; e < 4; ++e) s14[e] = *(const float4*)&s1w[e * 32 + k4 * 4];
                #pragma unroll
                for (int kk = 0; kk < 4; ++kk) {
                    float2 w2 = *(const float2*)&S->WbT[k4 * 4 + kk][2 * lane];
                    #pragma unroll
                    for (int e = 0; e < 4; ++e) {
                        float sv = (&s14[e].x)[kk];
                        acc0[e] = fmaf(sv, w2.x, acc0[e]);
                        acc1[e] = fmaf(sv, w2.y, acc1[e]);
                    }
                }
            }
            #pragma unroll
            for (int e = 0; e < 4; ++e) {
                float2 t2; t2.x = tanhf(acc0[e]); t2.y = tanhf(acc1[e]);
                *(float2*)&s2w[e * 64 + 2 * lane] = t2;
            }
        }
        __syncwarp();

        // ---- hg -> eng*imp ----
        float engimp[4];
        {
            float h0[4] = {0,0,0,0}, h1[4] = {0,0,0,0};
            #pragma unroll
            for (int m4 = 0; m4 < 16; ++m4) {
                float4 s24[4];
                #pragma unroll
                for (int e = 0; e < 4; ++e) s24[e] = *(const float4*)&s2w[e * 64 + m4 * 4];
                #pragma unroll
                for (int mm = 0; mm < 4; ++mm) {
                    float2 w2 = *(const float2*)&S->WshT[m4 * 4 + mm][2 * lane];
                    #pragma unroll
                    for (int e = 0; e < 4; ++e) {
                        float sv = (&s24[e].x)[mm];
                        h0[e] = fmaf(sv, w2.x, h0[e]);
                        h1[e] = fmaf(sv, w2.y, h1[e]);
                    }
                }
            }
            float we0 = S->Weng[2 * lane], we1 = S->Weng[2 * lane + 1];
            float wi0 = S->Wimp[2 * lane], wi1 = S->Wimp[2 * lane + 1];
            float bs0 = S->bsh[2 * lane],  bs1 = S->bsh[2 * lane + 1];
            #pragma unroll
            for (int e = 0; e < 4; ++e) {
                float g0 = fmaxf(h0[e] + bs0, 0.f);
                float g1 = fmaxf(h1[e] + bs1, 0.f);
                float pe = g0 * we0 + g1 * we1;
                float pi = g0 * wi0 + g1 * wi1;
                #pragma unroll
                for (int s = 16; s; s >>= 1) {
                    pe += __shfl_xor_sync(FULL, pe, s);
                    pi += __shfl_xor_sync(FULL, pi, s);
                }
                engimp[e] = sigm(pe + S->beng) * sigm(pi + S->bimp);
            }
        }

        // ---- halt -> gss ----
        {
            float ha[4] = {0,0,0,0};
            #pragma unroll
            for (int m4 = 0; m4 < 16; ++m4) {
                float4 s24[4];
                #pragma unroll
                for (int e = 0; e < 4; ++e) s24[e] = *(const float4*)&s2w[e * 64 + m4 * 4];
                #pragma unroll
                for (int mm = 0; mm < 4; ++mm) {
                    float hw = S->haltT[m4 * 4 + mm][lane];
                    #pragma unroll
                    for (int e = 0; e < 4; ++e)
                        ha[e] = fmaf((&s24[e].x)[mm], hw, ha[e]);
                }
            }
            float hb = S->haltb[lane >> 3];
            #pragma unroll
            for (int e = 0; e < 4; ++e) {
                float hv = sigm(ha[e] + hb);
                hv += __shfl_xor_sync(FULL, hv, 8);
                hv += __shfl_xor_sync(FULL, hv, 16);
                float g = engimp[e] * sur[e] * hv;
                if (lane < 8) gssw[e * 8 + lane] = g;
            }
        }
        __syncwarp();

        // ---- gate-term readout ----
        float4 s2m[4];
        #pragma unroll
        for (int e = 0; e < 4; ++e) s2m[e] = *(const float4*)&s2w[e * 64 + ((4 * lane) & 63)];

        float p[8][4];
        #pragma unroll
        for (int o = 0; o < 8; ++o)
            #pragma unroll
            for (int e = 0; e < 4; ++e) p[o][e] = 0.f;

        #pragma unroll
        for (int c = 0; c < 4; ++c) {
            float4 rsv[4];
            #pragma unroll
            for (int e = 0; e < 4; ++e) {
                float g = gssw[e * 8 + (lane >> 4) + 2 * c];
                rsv[e].x = g * s2m[e].x; rsv[e].y = g * s2m[e].y;
                rsv[e].z = g * s2m[e].z; rsv[e].w = g * s2m[e].w;
            }
            #pragma unroll
            for (int o = 0; o < 8; ++o) {
                float4 w4 = *(const float4*)&S->Wr[o][c * 128 + 4 * lane];
                #pragma unroll
                for (int e = 0; e < 4; ++e) {
                    p[o][e] = fmaf(rsv[e].x, w4.x, p[o][e]);
                    p[o][e] = fmaf(rsv[e].y, w4.y, p[o][e]);
                    p[o][e] = fmaf(rsv[e].z, w4.z, p[o][e]);
                    p[o][e] = fmaf(rsv[e].w, w4.w, p[o][e]);
                }
            }
        }
        #pragma unroll
        for (int o = 0; o < 8; ++o) {
            #pragma unroll
            for (int s = 16; s; s >>= 1) {
                #pragma unroll
                for (int e = 0; e < 4; ++e) p[o][e] += __shfl_xor_sync(FULL, p[o][e], s);
            }
            float pv = (lane == 0) ? p[o][0] : (lane == 1) ? p[o][1] :
                       (lane == 2) ? p[o][2] : p[o][3];
            if (lane < 4) out[(size_t)(e0 + lane) * 8 + o] = pv + S->bread[o];
        }
        __syncwarp();
    }
}

// ---------------- combine: out += g_outB ----------------------------------------------------
__global__ void combine_kernel(float* __restrict__ out, int n4) {
    int i = blockIdx.x * blockDim.x + threadIdx.x;
    if (i < n4) {
        float4 o = ((float4*)out)[i];
        float4 g = ((const float4*)g_outB)[i];
        o.x += g.x; o.y += g.y; o.z += g.z; o.w += g.w;
        ((float4*)out)[i] = o;
    }
}

extern "C" void kernel_launch(void* const* d_in, const int* in_sizes, int n_in,
                              void* d_out, int out_size) {
    const float* x        = (const float*)d_in[0];
    const float* H        = (const float*)d_in[1];
    const float* W_bit    = (const float*)d_in[2];
    const float* b_bit    = (const float*)d_in[3];
    const float* W_bridge = (const float*)d_in[4];
    const float* W_read   = (const float*)d_in[5];
    const float* b_read   = (const float*)d_in[6];
    const float* W_sh     = (const float*)d_in[7];
    const float* b_sh     = (const float*)d_in[8];
    const float* W_eng    = (const float*)d_in[9];
    const float* b_eng    = (const float*)d_in[10];
    const float* W_imp    = (const float*)d_in[11];
    const float* b_imp    = (const float*)d_in[12];
    const float* W_sur    = (const float*)d_in[13];
    const float* b_sur    = (const float*)d_in[14];
    const float* W_gate   = (const float*)d_in[15];
    const float* b_gate   = (const float*)d_in[16];
    const float* decays   = (const float*)d_in[17];
    const float* halt_w   = (const float*)d_in[18];
    const float* halt_b   = (const float*)d_in[19];
    const int B = in_sizes[0] / 8;
    float* out = (float*)d_out;

    cudaFuncSetAttribute(org_mixed, cudaFuncAttributeMaxDynamicSharedMemorySize,
                         (int)sizeof(SmemU));
    org_mixed<<<NBLK, 256, sizeof(SmemU)>>>(x, H, W_bit, b_bit, W_bridge, W_read,
                                            b_read, W_sh, b_sh, W_eng, b_eng,
                                            W_imp, b_imp, W_sur, b_sur, W_gate,
                                            b_gate, decays, halt_w, halt_b, out, B);

    int n4 = (B * 8) / 4;
    combine_kernel<<<(n4 + 255) / 256, 256>>>(out, n4);
}

// round 7
// speedup vs baseline: 1.4405x; 1.4405x over previous
#include <cuda_runtime.h>

#define GA 148           // MLP/gate blocks (1 per SM)
#define GB 296           // H-stream blocks (2 per SM)
#define NBLK (GA + GB)
#define MAXB 65536

__device__ float g_outB[MAXB * 8];  // H-stream partial outputs

__device__ __forceinline__ float sigm(float v) { return 1.0f / (1.0f + __expf(-v)); }

__device__ __forceinline__ unsigned long long ffma2(unsigned long long a,
                                                    unsigned long long b,
                                                    unsigned long long c) {
    unsigned long long d;
    asm("fma.rn.f32x2 %0, %1, %2, %3;" : "=l"(d) : "l"(a), "l"(b), "l"(c));
    return d;
}
union f4u { float4 f; unsigned long long u[2]; };

// ---------------- shared layouts ------------------------------------------------------------
struct SmemA {                      // ~64.7 KB
    float Wr[8][512];
    float WbT[32][64];
    float WshT[64][64];
    float haltT[64][32];
    float s2s[8][4][64];
    float s1s[8][4][32];
    float gss[8][4][8];
    float WbitT[8][32];
    float Weng[64], Wimp[64];
    float Wsur[32], Wgate[32];
    float bbit[32], bsh[64];
    float bread[8];
    float haltb[4];
    float beng, bimp, bsur, bgate;
};
struct SmemB {                      // 24 KB
    float dg[2048];
    float Wr[8][512];
};
union SmemU { SmemA a; SmemB b; };

__global__ void __launch_bounds__(256, 3)
org_mixed(const float* __restrict__ x, const float* __restrict__ H,
          const float* __restrict__ W_bit, const float* __restrict__ b_bit,
          const float* __restrict__ W_bridge, const float* __restrict__ W_read,
          const float* __restrict__ b_read, const float* __restrict__ W_sh,
          const float* __restrict__ b_sh, const float* __restrict__ W_eng,
          const float* __restrict__ b_eng, const float* __restrict__ W_imp,
          const float* __restrict__ b_imp, const float* __restrict__ W_sur,
          const float* __restrict__ b_sur, const float* __restrict__ W_gate,
          const float* __restrict__ b_gate, const float* __restrict__ decays,
          const float* __restrict__ halt_w, const float* __restrict__ halt_b,
          float* __restrict__ out, int B)
{
    extern __shared__ float smraw[];
    SmemU* Su = reinterpret_cast<SmemU*>(smraw);
    const int tid = threadIdx.x;
    const int warp = tid >> 5, lane = tid & 31;
    const unsigned FULL = 0xffffffffu;

    if (blockIdx.x >= GA) {
        // ===================== B path: register-fed H stream (round-4 proven) =============
        SmemB* Sb = &Su->b;
        for (int i = tid; i < 2048; i += 256) Sb->dg[i] = sigm(decays[i]);
        for (int i = tid; i < 4096; i += 256) (&Sb->Wr[0][0])[i] = 0.25f * W_read[i];
        __syncthreads();

        for (int b0 = (((int)blockIdx.x - GA) * 8 + warp) * 2; b0 < B; b0 += GB * 16) {
            const float4* H0 = (const float4*)H + (size_t)b0 * 512;
            f4u rs[2][4];
            #pragma unroll
            for (int e = 0; e < 2; ++e)
                #pragma unroll
                for (int c = 0; c < 4; ++c) rs[e][c].f = make_float4(0.f, 0.f, 0.f, 0.f);

            #pragma unroll
            for (int l = 0; l < 4; ++l) {
                f4u t[2][4];
                #pragma unroll
                for (int e = 0; e < 2; ++e)
                    #pragma unroll
                    for (int c = 0; c < 4; ++c)
                        t[e][c].f = __ldcs(H0 + (size_t)e * 512 + l * 128 + c * 32 + lane);
                #pragma unroll
                for (int c = 0; c < 4; ++c) {
                    f4u d; d.f = *(const float4*)&Sb->dg[l * 512 + c * 128 + 4 * lane];
                    #pragma unroll
                    for (int e = 0; e < 2; ++e) {
                        rs[e][c].u[0] = ffma2(t[e][c].u[0], d.u[0], rs[e][c].u[0]);
                        rs[e][c].u[1] = ffma2(t[e][c].u[1], d.u[1], rs[e][c].u[1]);
                    }
                }
            }
            // readout: p[e][o] = sum_j rs * Wr4[o][j]
            #pragma unroll
            for (int o = 0; o < 8; ++o) {
                unsigned long long a0 = 0ull, a1 = 0ull, c0 = 0ull, c1 = 0ull;
                #pragma unroll
                for (int c = 0; c < 4; ++c) {
                    f4u w; w.f = *(const float4*)&Sb->Wr[o][c * 128 + 4 * lane];
                    a0 = ffma2(rs[0][c].u[0], w.u[0], a0);
                    a1 = ffma2(rs[0][c].u[1], w.u[1], a1);
                    c0 = ffma2(rs[1][c].u[0], w.u[0], c0);
                    c1 = ffma2(rs[1][c].u[1], w.u[1], c1);
                }
                f4u pa; pa.u[0] = a0; pa.u[1] = a1;
                f4u pc; pc.u[0] = c0; pc.u[1] = c1;
                float p0 = (pa.f.x + pa.f.y) + (pa.f.z + pa.f.w);
                float p1 = (pc.f.x + pc.f.y) + (pc.f.z + pc.f.w);
                #pragma unroll
                for (int s = 16; s; s >>= 1) {
                    p0 += __shfl_xor_sync(FULL, p0, s);
                    p1 += __shfl_xor_sync(FULL, p1, s);
                }
                if (lane == o)      g_outB[(size_t)b0 * 8 + o]       = p0;
                if (lane == 16 + o) g_outB[(size_t)(b0 + 1) * 8 + o] = p1;
            }
        }
        return;
    }

    // ===================== A path: MLP + gate-term readout =============================
    SmemA* S = &Su->a;
    for (int i = tid; i < 4096; i += 256) (&S->Wr[0][0])[i] = 0.25f * W_read[i];
    for (int i = tid; i < 2048; i += 256) { int k = i >> 6, m = i & 63; (&S->WbT[0][0])[i]   = W_bridge[m * 32 + k]; }
    for (int i = tid; i < 4096; i += 256) { int m = i >> 6, o = i & 63; (&S->WshT[0][0])[i]  = W_sh[o * 64 + m]; }
    for (int i = tid; i < 2048; i += 256) { int m = i >> 5, s = i & 31; (&S->haltT[0][0])[i] = halt_w[s * 64 + m]; }
    (&S->WbitT[0][0])[tid] = W_bit[(tid & 31) * 8 + (tid >> 5)];
    if (tid < 64) { S->Weng[tid] = W_eng[tid]; S->Wimp[tid] = W_imp[tid]; S->bsh[tid] = b_sh[tid]; }
    if (tid < 32) { S->Wsur[tid] = W_sur[tid]; S->Wgate[tid] = W_gate[tid]; S->bbit[tid] = b_bit[tid]; }
    if (tid < 8)  S->bread[tid] = b_read[tid];
    if (tid < 4)  S->haltb[tid] = halt_b[tid];
    if (tid == 0) { S->beng = b_eng[0]; S->bimp = b_imp[0]; S->bsur = b_sur[0]; S->bgate = b_gate[0]; }
    __syncthreads();

    float* s1w  = &S->s1s[warp][0][0];
    float* s2w  = &S->s2s[warp][0][0];
    float* gssw = &S->gss[warp][0][0];

    for (int e0 = blockIdx.x * 32 + warp * 4; e0 < B; e0 += GA * 32) {
        // ---- s1 ----
        float xv = x[(size_t)e0 * 8 + lane];
        float s1v[4];
        #pragma unroll
        for (int e = 0; e < 4; ++e) {
            float a = S->bbit[lane];
            #pragma unroll
            for (int j = 0; j < 8; ++j) {
                float xj = __shfl_sync(FULL, xv, e * 8 + j);
                a = fmaf(xj, S->WbitT[j][lane], a);
            }
            s1v[e] = a;
            s1w[e * 32 + lane] = a;
        }
        // ---- surprise ----
        float sur[4];
        #pragma unroll
        for (int e = 0; e < 4; ++e) {
            float a = s1v[e] * S->Wsur[lane];
            float b = s1v[e] * S->Wgate[lane];
            #pragma unroll
            for (int s = 16; s; s >>= 1) {
                a += __shfl_xor_sync(FULL, a, s);
                b += __shfl_xor_sync(FULL, b, s);
            }
            sur[e] = sigm(a + S->bsur) * sigm(b + S->bgate);
        }
        __syncwarp();

        // ---- s2 = tanh(s1 @ Wb^T) ----
        {
            float acc0[4] = {0,0,0,0}, acc1[4] = {0,0,0,0};
            #pragma unroll
            for (int k4 = 0; k4 < 8; ++k4) {
                float4 s14[4];
                #pragma unroll
                for (int e = 0; e < 4; ++e) s14[e] = *(const float4*)&s1w[e * 32 + k4 * 4];
                #pragma unroll
                for (int kk = 0; kk < 4; ++kk) {
                    float2 w2 = *(const float2*)&S->WbT[k4 * 4 + kk][2 * lane];
                    #pragma unroll
                    for (int e = 0; e < 4; ++e) {
                        float sv = (&s14[e].x)[kk];
                        acc0[e] = fmaf(sv, w2.x, acc0[e]);
                        acc1[e] = fmaf(sv, w2.y, acc1[e]);
                    }
                }
            }
            #pragma unroll
            for (int e = 0; e < 4; ++e) {
                float2 t2; t2.x = tanhf(acc0[e]); t2.y = tanhf(acc1[e]);
                *(float2*)&s2w[e * 64 + 2 * lane] = t2;
            }
        }
        __syncwarp();

        // ---- merged hg + halt loop: share the s2 LDS traffic --------------------------
        float engimp[4];
        float ha[4] = {0,0,0,0};
        {
            float h0[4] = {0,0,0,0}, h1[4] = {0,0,0,0};
            #pragma unroll
            for (int m4 = 0; m4 < 16; ++m4) {
                float4 s24[4];
                #pragma unroll
                for (int e = 0; e < 4; ++e) s24[e] = *(const float4*)&s2w[e * 64 + m4 * 4];
                #pragma unroll
                for (int mm = 0; mm < 4; ++mm) {
                    float2 w2 = *(const float2*)&S->WshT[m4 * 4 + mm][2 * lane];
                    float hw  = S->haltT[m4 * 4 + mm][lane];
                    #pragma unroll
                    for (int e = 0; e < 4; ++e) {
                        float sv = (&s24[e].x)[mm];
                        h0[e] = fmaf(sv, w2.x, h0[e]);
                        h1[e] = fmaf(sv, w2.y, h1[e]);
                        ha[e] = fmaf(sv, hw,   ha[e]);
                    }
                }
            }
            float we0 = S->Weng[2 * lane], we1 = S->Weng[2 * lane + 1];
            float wi0 = S->Wimp[2 * lane], wi1 = S->Wimp[2 * lane + 1];
            float bs0 = S->bsh[2 * lane],  bs1 = S->bsh[2 * lane + 1];
            #pragma unroll
            for (int e = 0; e < 4; ++e) {
                float g0 = fmaxf(h0[e] + bs0, 0.f);
                float g1 = fmaxf(h1[e] + bs1, 0.f);
                float pe = g0 * we0 + g1 * we1;
                float pi = g0 * wi0 + g1 * wi1;
                #pragma unroll
                for (int s = 16; s; s >>= 1) {
                    pe += __shfl_xor_sync(FULL, pe, s);
                    pi += __shfl_xor_sync(FULL, pi, s);
                }
                engimp[e] = sigm(pe + S->beng) * sigm(pi + S->bimp);
            }
        }

        // ---- halt sigmoid -> gss ----
        {
            float hb = S->haltb[lane >> 3];
            #pragma unroll
            for (int e = 0; e < 4; ++e) {
                float hv = sigm(ha[e] + hb);
                hv += __shfl_xor_sync(FULL, hv, 8);
                hv += __shfl_xor_sync(FULL, hv, 16);
                float g = engimp[e] * sur[e] * hv;
                if (lane < 8) gssw[e * 8 + lane] = g;
            }
        }
        __syncwarp();

        // ---- gate-term readout ----
        float4 s2m[4];
        #pragma unroll
        for (int e = 0; e < 4; ++e) s2m[e] = *(const float4*)&s2w[e * 64 + ((4 * lane) & 63)];

        float p[8][4];
        #pragma unroll
        for (int o = 0; o < 8; ++o)
            #pragma unroll
            for (int e = 0; e < 4; ++e) p[o][e] = 0.f;

        #pragma unroll
        for (int c = 0; c < 4; ++c) {
            float4 rsv[4];
            #pragma unroll
            for (int e = 0; e < 4; ++e) {
                float g = gssw[e * 8 + (lane >> 4) + 2 * c];
                rsv[e].x = g * s2m[e].x; rsv[e].y = g * s2m[e].y;
                rsv[e].z = g * s2m[e].z; rsv[e].w = g * s2m[e].w;
            }
            #pragma unroll
            for (int o = 0; o < 8; ++o) {
                float4 w4 = *(const float4*)&S->Wr[o][c * 128 + 4 * lane];
                #pragma unroll
                for (int e = 0; e < 4; ++e) {
                    p[o][e] = fmaf(rsv[e].x, w4.x, p[o][e]);
                    p[o][e] = fmaf(rsv[e].y, w4.y, p[o][e]);
                    p[o][e] = fmaf(rsv[e].z, w4.z, p[o][e]);
                    p[o][e] = fmaf(rsv[e].w, w4.w, p[o][e]);
                }
            }
        }
        #pragma unroll
        for (int o = 0; o < 8; ++o) {
            #pragma unroll
            for (int s = 16; s; s >>= 1) {
                #pragma unroll
                for (int e = 0; e < 4; ++e) p[o][e] += __shfl_xor_sync(FULL, p[o][e], s);
            }
            float pv = (lane == 0) ? p[o][0] : (lane == 1) ? p[o][1] :
                       (lane == 2) ? p[o][2] : p[o][3];
            if (lane < 4) out[(size_t)(e0 + lane) * 8 + o] = pv + S->bread[o];
        }
        __syncwarp();
    }
}

// ---------------- combine: out += g_outB ----------------------------------------------------
__global__ void combine_kernel(float* __restrict__ out, int n4) {
    int i = blockIdx.x * blockDim.x + threadIdx.x;
    if (i < n4) {
        float4 o = ((float4*)out)[i];
        float4 g = ((const float4*)g_outB)[i];
        o.x += g.x; o.y += g.y; o.z += g.z; o.w += g.w;
        ((float4*)out)[i] = o;
    }
}

extern "C" void kernel_launch(void* const* d_in, const int* in_sizes, int n_in,
                              void* d_out, int out_size) {
    const float* x        = (const float*)d_in[0];
    const float* H        = (const float*)d_in[1];
    const float* W_bit    = (const float*)d_in[2];
    const float* b_bit    = (const float*)d_in[3];
    const float* W_bridge = (const float*)d_in[4];
    const float* W_read   = (const float*)d_in[5];
    const float* b_read   = (const float*)d_in[6];
    const float* W_sh     = (const float*)d_in[7];
    const float* b_sh     = (const float*)d_in[8];
    const float* W_eng    = (const float*)d_in[9];
    const float* b_eng    = (const float*)d_in[10];
    const float* W_imp    = (const float*)d_in[11];
    const float* b_imp    = (const float*)d_in[12];
    const float* W_sur    = (const float*)d_in[13];
    const float* b_sur    = (const float*)d_in[14];
    const float* W_gate   = (const float*)d_in[15];
    const float* b_gate   = (const float*)d_in[16];
    const float* decays   = (const float*)d_in[17];
    const float* halt_w   = (const float*)d_in[18];
    const float* halt_b   = (const float*)d_in[19];
    const int B = in_sizes[0] / 8;
    float* out = (float*)d_out;

    cudaFuncSetAttribute(org_mixed, cudaFuncAttributeMaxDynamicSharedMemorySize,
                         (int)sizeof(SmemU));
    org_mixed<<<NBLK, 256, sizeof(SmemU)>>>(x, H, W_bit, b_bit, W_bridge, W_read,
                                            b_read, W_sh, b_sh, W_eng, b_eng,
                                            W_imp, b_imp, W_sur, b_sur, W_gate,
                                            b_gate, decays, halt_w, halt_b, out, B);

    int n4 = (B * 8) / 4;
    combine_kernel<<<(n4 + 255) / 256, 256>>>(out, n4);
}

// round 8
// speedup vs baseline: 1.7308x; 1.2016x over previous
#include <cuda_runtime.h>

#define GAB 444          // blocks for both phases (3 per SM)
#define MAXB 65536

__device__ float g_sg[MAXB * 72];   // per-elem: s2[64] then gss[8]

__device__ __forceinline__ float sigm(float v) { return 1.0f / (1.0f + __expf(-v)); }

__device__ __forceinline__ unsigned long long ffma2(unsigned long long a,
                                                    unsigned long long b,
                                                    unsigned long long c) {
    unsigned long long d;
    asm("fma.rn.f32x2 %0, %1, %2, %3;" : "=l"(d) : "l"(a), "l"(b), "l"(c));
    return d;
}
union f4u { float4 f; unsigned long long u[2]; };

// =================== Kernel A: MLP -> s2, gss =================================================
struct SmemA {                      // ~47 KB
    float WbT[32][64];
    float WshT[64][64];
    float haltT[64][32];
    float s2s[8][4][64];
    float s1s[8][4][32];
    float WbitT[8][32];
    float Weng[64], Wimp[64];
    float Wsur[32], Wgate[32];
    float bbit[32], bsh[64];
    float haltb[4];
    float beng, bimp, bsur, bgate;
};

__global__ void __launch_bounds__(256, 3)
org_mlp(const float* __restrict__ x,
        const float* __restrict__ W_bit, const float* __restrict__ b_bit,
        const float* __restrict__ W_bridge, const float* __restrict__ W_sh,
        const float* __restrict__ b_sh, const float* __restrict__ W_eng,
        const float* __restrict__ b_eng, const float* __restrict__ W_imp,
        const float* __restrict__ b_imp, const float* __restrict__ W_sur,
        const float* __restrict__ b_sur, const float* __restrict__ W_gate,
        const float* __restrict__ b_gate, const float* __restrict__ halt_w,
        const float* __restrict__ halt_b, int B)
{
    extern __shared__ float smraw[];
    SmemA* S = reinterpret_cast<SmemA*>(smraw);
    const int tid = threadIdx.x;
    const int warp = tid >> 5, lane = tid & 31;
    const unsigned FULL = 0xffffffffu;

    for (int i = tid; i < 2048; i += 256) { int k = i >> 6, m = i & 63; (&S->WbT[0][0])[i]   = W_bridge[m * 32 + k]; }
    for (int i = tid; i < 4096; i += 256) { int m = i >> 6, o = i & 63; (&S->WshT[0][0])[i]  = W_sh[o * 64 + m]; }
    for (int i = tid; i < 2048; i += 256) { int m = i >> 5, s = i & 31; (&S->haltT[0][0])[i] = halt_w[s * 64 + m]; }
    (&S->WbitT[0][0])[tid] = W_bit[(tid & 31) * 8 + (tid >> 5)];
    if (tid < 64) { S->Weng[tid] = W_eng[tid]; S->Wimp[tid] = W_imp[tid]; S->bsh[tid] = b_sh[tid]; }
    if (tid < 32) { S->Wsur[tid] = W_sur[tid]; S->Wgate[tid] = W_gate[tid]; S->bbit[tid] = b_bit[tid]; }
    if (tid < 4)  S->haltb[tid] = halt_b[tid];
    if (tid == 0) { S->beng = b_eng[0]; S->bimp = b_imp[0]; S->bsur = b_sur[0]; S->bgate = b_gate[0]; }
    __syncthreads();

    float* s1w = &S->s1s[warp][0][0];
    float* s2w = &S->s2s[warp][0][0];

    for (int e0 = blockIdx.x * 32 + warp * 4; e0 < B; e0 += GAB * 32) {
        // ---- s1 ----
        float xv = x[(size_t)e0 * 8 + lane];
        float s1v[4];
        #pragma unroll
        for (int e = 0; e < 4; ++e) {
            float a = S->bbit[lane];
            #pragma unroll
            for (int j = 0; j < 8; ++j) {
                float xj = __shfl_sync(FULL, xv, e * 8 + j);
                a = fmaf(xj, S->WbitT[j][lane], a);
            }
            s1v[e] = a;
            s1w[e * 32 + lane] = a;
        }
        // ---- surprise ----
        float sur[4];
        #pragma unroll
        for (int e = 0; e < 4; ++e) {
            float a = s1v[e] * S->Wsur[lane];
            float b = s1v[e] * S->Wgate[lane];
            #pragma unroll
            for (int s = 16; s; s >>= 1) {
                a += __shfl_xor_sync(FULL, a, s);
                b += __shfl_xor_sync(FULL, b, s);
            }
            sur[e] = sigm(a + S->bsur) * sigm(b + S->bgate);
        }
        __syncwarp();

        // ---- s2 = tanh(s1 @ Wb^T); store to smem AND global ----
        {
            float acc0[4] = {0,0,0,0}, acc1[4] = {0,0,0,0};
            #pragma unroll
            for (int k4 = 0; k4 < 8; ++k4) {
                float4 s14[4];
                #pragma unroll
                for (int e = 0; e < 4; ++e) s14[e] = *(const float4*)&s1w[e * 32 + k4 * 4];
                #pragma unroll
                for (int kk = 0; kk < 4; ++kk) {
                    float2 w2 = *(const float2*)&S->WbT[k4 * 4 + kk][2 * lane];
                    #pragma unroll
                    for (int e = 0; e < 4; ++e) {
                        float sv = (&s14[e].x)[kk];
                        acc0[e] = fmaf(sv, w2.x, acc0[e]);
                        acc1[e] = fmaf(sv, w2.y, acc1[e]);
                    }
                }
            }
            #pragma unroll
            for (int e = 0; e < 4; ++e) {
                float2 t2; t2.x = tanhf(acc0[e]); t2.y = tanhf(acc1[e]);
                *(float2*)&s2w[e * 64 + 2 * lane] = t2;
                *(float2*)&g_sg[(size_t)(e0 + e) * 72 + 2 * lane] = t2;
            }
        }
        __syncwarp();

        // ---- merged hg + halt loop ----
        float engimp[4];
        float ha[4] = {0,0,0,0};
        {
            float h0[4] = {0,0,0,0}, h1[4] = {0,0,0,0};
            #pragma unroll
            for (int m4 = 0; m4 < 16; ++m4) {
                float4 s24[4];
                #pragma unroll
                for (int e = 0; e < 4; ++e) s24[e] = *(const float4*)&s2w[e * 64 + m4 * 4];
                #pragma unroll
                for (int mm = 0; mm < 4; ++mm) {
                    float2 w2 = *(const float2*)&S->WshT[m4 * 4 + mm][2 * lane];
                    float hw  = S->haltT[m4 * 4 + mm][lane];
                    #pragma unroll
                    for (int e = 0; e < 4; ++e) {
                        float sv = (&s24[e].x)[mm];
                        h0[e] = fmaf(sv, w2.x, h0[e]);
                        h1[e] = fmaf(sv, w2.y, h1[e]);
                        ha[e] = fmaf(sv, hw,   ha[e]);
                    }
                }
            }
            float we0 = S->Weng[2 * lane], we1 = S->Weng[2 * lane + 1];
            float wi0 = S->Wimp[2 * lane], wi1 = S->Wimp[2 * lane + 1];
            float bs0 = S->bsh[2 * lane],  bs1 = S->bsh[2 * lane + 1];
            #pragma unroll
            for (int e = 0; e < 4; ++e) {
                float g0 = fmaxf(h0[e] + bs0, 0.f);
                float g1 = fmaxf(h1[e] + bs1, 0.f);
                float pe = g0 * we0 + g1 * we1;
                float pi = g0 * wi0 + g1 * wi1;
                #pragma unroll
                for (int s = 16; s; s >>= 1) {
                    pe += __shfl_xor_sync(FULL, pe, s);
                    pi += __shfl_xor_sync(FULL, pi, s);
                }
                engimp[e] = sigm(pe + S->beng) * sigm(pi + S->bimp);
            }
        }

        // ---- halt sigmoid -> gss -> global ----
        float hb = S->haltb[lane >> 3];
        #pragma unroll
        for (int e = 0; e < 4; ++e) {
            float hv = sigm(ha[e] + hb);
            hv += __shfl_xor_sync(FULL, hv, 8);
            hv += __shfl_xor_sync(FULL, hv, 16);
            float g = engimp[e] * sur[e] * hv;
            if (lane < 8) g_sg[(size_t)(e0 + e) * 72 + 64 + lane] = g;
        }
        __syncwarp();
    }
}

// =================== Kernel B: H stream + gate fold + readout =================================
struct SmemB {                      // ~24.6 KB
    float dg[2048];
    float Wr[8][512];
    float bread[8];
};

__global__ void __launch_bounds__(256, 3)
org_stream(const float* __restrict__ H, const float* __restrict__ W_read,
           const float* __restrict__ b_read, const float* __restrict__ decays,
           float* __restrict__ out, int B)
{
    extern __shared__ float smraw[];
    SmemB* Sb = reinterpret_cast<SmemB*>(smraw);
    const int tid = threadIdx.x;
    const int warp = tid >> 5, lane = tid & 31;
    const unsigned FULL = 0xffffffffu;

    for (int i = tid; i < 2048; i += 256) Sb->dg[i] = sigm(decays[i]);
    for (int i = tid; i < 4096; i += 256) (&Sb->Wr[0][0])[i] = 0.25f * W_read[i];
    if (tid < 8) Sb->bread[tid] = b_read[tid];
    __syncthreads();

    for (int b0 = ((int)blockIdx.x * 8 + warp) * 2; b0 < B; b0 += GAB * 16) {
        const float4* H0 = (const float4*)H + (size_t)b0 * 512;
        f4u rs[2][4];
        #pragma unroll
        for (int e = 0; e < 2; ++e)
            #pragma unroll
            for (int c = 0; c < 4; ++c) rs[e][c].f = make_float4(0.f, 0.f, 0.f, 0.f);

        #pragma unroll
        for (int l = 0; l < 4; ++l) {
            f4u t[2][4];
            #pragma unroll
            for (int e = 0; e < 2; ++e)
                #pragma unroll
                for (int c = 0; c < 4; ++c)
                    t[e][c].f = __ldcs(H0 + (size_t)e * 512 + l * 128 + c * 32 + lane);
            #pragma unroll
            for (int c = 0; c < 4; ++c) {
                f4u d; d.f = *(const float4*)&Sb->dg[l * 512 + c * 128 + 4 * lane];
                #pragma unroll
                for (int e = 0; e < 2; ++e) {
                    rs[e][c].u[0] = ffma2(t[e][c].u[0], d.u[0], rs[e][c].u[0]);
                    rs[e][c].u[1] = ffma2(t[e][c].u[1], d.u[1], rs[e][c].u[1]);
                }
            }
        }

        // ---- fold gate term: rs[e][c] += gss[r(c)] * s2[m] ----
        #pragma unroll
        for (int e = 0; e < 2; ++e) {
            const float* sg = &g_sg[(size_t)(b0 + e) * 72];
            float4 s2m = *(const float4*)&sg[(4 * lane) & 63];
            #pragma unroll
            for (int c = 0; c < 4; ++c) {
                float g = sg[64 + (lane >> 4) + 2 * c];
                rs[e][c].f.x = fmaf(g, s2m.x, rs[e][c].f.x);
                rs[e][c].f.y = fmaf(g, s2m.y, rs[e][c].f.y);
                rs[e][c].f.z = fmaf(g, s2m.z, rs[e][c].f.z);
                rs[e][c].f.w = fmaf(g, s2m.w, rs[e][c].f.w);
            }
        }

        // ---- readout: out[e][o] = sum_j rs * Wr4[o][j] + bread[o] ----
        #pragma unroll
        for (int o = 0; o < 8; ++o) {
            unsigned long long a0 = 0ull, a1 = 0ull, c0 = 0ull, c1 = 0ull;
            #pragma unroll
            for (int c = 0; c < 4; ++c) {
                f4u w; w.f = *(const float4*)&Sb->Wr[o][c * 128 + 4 * lane];
                a0 = ffma2(rs[0][c].u[0], w.u[0], a0);
                a1 = ffma2(rs[0][c].u[1], w.u[1], a1);
                c0 = ffma2(rs[1][c].u[0], w.u[0], c0);
                c1 = ffma2(rs[1][c].u[1], w.u[1], c1);
            }
            f4u pa; pa.u[0] = a0; pa.u[1] = a1;
            f4u pc; pc.u[0] = c0; pc.u[1] = c1;
            float p0 = (pa.f.x + pa.f.y) + (pa.f.z + pa.f.w);
            float p1 = (pc.f.x + pc.f.y) + (pc.f.z + pc.f.w);
            #pragma unroll
            for (int s = 16; s; s >>= 1) {
                p0 += __shfl_xor_sync(FULL, p0, s);
                p1 += __shfl_xor_sync(FULL, p1, s);
            }
            if (lane == o)      out[(size_t)b0 * 8 + o]       = p0 + Sb->bread[o];
            if (lane == 16 + o) out[(size_t)(b0 + 1) * 8 + o] = p1 + Sb->bread[o];
        }
    }
}

extern "C" void kernel_launch(void* const* d_in, const int* in_sizes, int n_in,
                              void* d_out, int out_size) {
    const float* x        = (const float*)d_in[0];
    const float* H        = (const float*)d_in[1];
    const float* W_bit    = (const float*)d_in[2];
    const float* b_bit    = (const float*)d_in[3];
    const float* W_bridge = (const float*)d_in[4];
    const float* W_read   = (const float*)d_in[5];
    const float* b_read   = (const float*)d_in[6];
    const float* W_sh     = (const float*)d_in[7];
    const float* b_sh     = (const float*)d_in[8];
    const float* W_eng    = (const float*)d_in[9];
    const float* b_eng    = (const float*)d_in[10];
    const float* W_imp    = (const float*)d_in[11];
    const float* b_imp    = (const float*)d_in[12];
    const float* W_sur    = (const float*)d_in[13];
    const float* b_sur    = (const float*)d_in[14];
    const float* W_gate   = (const float*)d_in[15];
    const float* b_gate   = (const float*)d_in[16];
    const float* decays   = (const float*)d_in[17];
    const float* halt_w   = (const float*)d_in[18];
    const float* halt_b   = (const float*)d_in[19];
    const int B = in_sizes[0] / 8;
    float* out = (float*)d_out;

    cudaFuncSetAttribute(org_mlp, cudaFuncAttributeMaxDynamicSharedMemorySize,
                         (int)sizeof(SmemA));
    cudaFuncSetAttribute(org_stream, cudaFuncAttributeMaxDynamicSharedMemorySize,
                         (int)sizeof(SmemB));

    org_mlp<<<GAB, 256, sizeof(SmemA)>>>(x, W_bit, b_bit, W_bridge, W_sh, b_sh,
                                         W_eng, b_eng, W_imp, b_imp, W_sur, b_sur,
                                         W_gate, b_gate, halt_w, halt_b, B);

    org_stream<<<GAB, 256, sizeof(SmemB)>>>(H, W_read, b_read, decays, out, B);
}